// round 1
// baseline (speedup 1.0000x reference)
#include <cuda_runtime.h>

#define NQ     18
#define NREPS  3
#define NBATCH 64
#define IDIM   32

__device__ __forceinline__ float2 cmul(float2 a, float2 b) {
    return make_float2(a.x * b.x - a.y * b.y, a.x * b.y + a.y * b.x);
}
__device__ __forceinline__ float2 cmulc(float2 a, float2 b) {   // a * conj(b)
    return make_float2(a.x * b.x + a.y * b.y, a.y * b.x - a.x * b.y);
}
__device__ __forceinline__ float2 cadd(float2 a, float2 b) {
    return make_float2(a.x + b.x, a.y + b.y);
}

// One block per batch element. Exact MPS/transfer-matrix contraction:
//   - CNOT staircase == prefix-XOR basis permutation
//   - bond dimension exactly 8 = 2^REPS (one crossing gate per cut per rep)
//   - G_k[z] are 8x8; left/right 8x8 density environments give all <Z_w>.
__global__ __launch_bounds__(256, 1) void qenc_kernel(
    const float* __restrict__ xin,   // (64, 32) float32
    const float* __restrict__ vp,    // (3, 18, 2) float32
    float* __restrict__ out)         // (64, 18) float32
{
    const int b   = blockIdx.x;
    const int tid = threadIdx.x;

    __shared__ float2 G[NQ][2][8][8];        // site tensors G[k][z][p][n]
    __shared__ float2 rhoL[NQ][8][8];        // rho^(0..17)
    __shared__ float2 sigR[NQ + 1][8][8];    // sigma^(1..18) at index k
    __shared__ float2 tmpL[2][8][8];
    __shared__ float2 tmpR[2][8][8];
    __shared__ float  B3s[NQ][2][2];
    __shared__ float  C3s[NQ][2][2];         // A3 * B2
    __shared__ float  C2s[NQ][2][2];         // A2 * B1
    __shared__ float2 ws[NQ][2];             // A1 * u   (batch-dependent, complex)
    __shared__ float  zred[NQ][8];

    // ---- per-site 2x2 matrices -------------------------------------------
    if (tid < NQ) {
        const int k = tid;
        float cc[6], ssn[6];
        #pragma unroll
        for (int r = 0; r < NREPS; ++r) {
            #pragma unroll
            for (int c = 0; c < 2; ++c) {
                const float th = vp[(r * NQ + k) * 2 + c];
                sincosf(0.5f * th, &ssn[r * 2 + c], &cc[r * 2 + c]);
            }
        }
        // RY(th) = [[c,-s],[s,c]]; order: A1,B1,A2,B2,A3,B3
        const float A1[2][2] = {{cc[0], -ssn[0]}, {ssn[0], cc[0]}};
        const float B1[2][2] = {{cc[1], -ssn[1]}, {ssn[1], cc[1]}};
        const float A2[2][2] = {{cc[2], -ssn[2]}, {ssn[2], cc[2]}};
        const float B2[2][2] = {{cc[3], -ssn[3]}, {ssn[3], cc[3]}};
        const float A3[2][2] = {{cc[4], -ssn[4]}, {ssn[4], cc[4]}};
        B3s[k][0][0] = cc[5];   B3s[k][0][1] = -ssn[5];
        B3s[k][1][0] = ssn[5];  B3s[k][1][1] = cc[5];
        #pragma unroll
        for (int i = 0; i < 2; ++i) {
            #pragma unroll
            for (int j = 0; j < 2; ++j) {
                C3s[k][i][j] = A3[i][0] * B2[0][j] + A3[i][1] * B2[1][j];
                C2s[k][i][j] = A2[i][0] * B1[0][j] + A2[i][1] * B1[1][j];
            }
        }
        // RX(x)|0> = (cos(x/2), -i sin(x/2));  w[s] = A1[s][0]*u0 + A1[s][1]*u1
        const float xv = xin[b * IDIM + k];
        float sx, cx;
        sincosf(0.5f * xv, &sx, &cx);
        ws[k][0] = make_float2(A1[0][0] * cx, -A1[0][1] * sx);
        ws[k][1] = make_float2(A1[1][0] * cx, -A1[1][1] * sx);
    }
    __syncthreads();

    // ---- build G[k][z] (8x8) ---------------------------------------------
    // bond index = t1 + 2*t2 + 4*t3 (intermediate post-permutation bits of reps 1..3)
    for (int i = tid; i < NQ * 128; i += 256) {
        const int k  = i >> 7;
        const int z  = (i >> 6) & 1;
        const int p  = (i >> 3) & 7;
        const int n  = i & 7;
        const int n1 = n & 1, n2 = (n >> 1) & 1, n3 = (n >> 2) & 1;
        const int p1 = p & 1, p2 = (p >> 1) & 1, p3 = (p >> 2) & 1;
        const float coef = B3s[k][z][n3] * C3s[k][n3 ^ p3][n2] * C2s[k][n2 ^ p2][n1];
        const float2 wv  = ws[k][n1 ^ p1];
        G[k][z][p][n] = make_float2(coef * wv.x, coef * wv.y);
    }
    if (tid < 64) {
        rhoL[0][tid >> 3][tid & 7] = make_float2(tid == 0 ? 1.f : 0.f, 0.f);
    } else if (tid < 128) {
        const int j = tid - 64;
        sigR[NQ][j >> 3][j & 7] = make_float2(1.f, 0.f);
    }
    __syncthreads();

    // ---- simultaneous left (threads 0..127) and right (128..255) sweeps ---
    const int half = tid >> 7;
    const int lt   = tid & 127;
    const int z0   = lt >> 6;
    const int i0   = (lt >> 3) & 7;
    const int j0   = lt & 7;

    for (int t = 0; t < NQ - 1; ++t) {
        // stage 1:  tmpL[z] = G[t][z]^T * rho     |  tmpR[z] = G[17-t][z] * sigma
        if (half == 0) {
            float2 acc = make_float2(0.f, 0.f);
            #pragma unroll
            for (int a = 0; a < 8; ++a)
                acc = cadd(acc, cmul(G[t][z0][a][i0], rhoL[t][a][j0]));
            tmpL[z0][i0][j0] = acc;
        } else {
            const int kR = NQ - 1 - t;
            float2 acc = make_float2(0.f, 0.f);
            #pragma unroll
            for (int a = 0; a < 8; ++a)
                acc = cadd(acc, cmul(G[kR][z0][i0][a], sigR[kR + 1][a][j0]));
            tmpR[z0][i0][j0] = acc;
        }
        __syncthreads();
        // stage 2:  rho' = sum_z tmpL[z] * conj(G[t][z]) | sig' = sum_z tmpR[z] * G[kR][z]^dag
        if (lt < 64) {
            if (half == 0) {
                float2 acc = make_float2(0.f, 0.f);
                #pragma unroll
                for (int z = 0; z < 2; ++z)
                    #pragma unroll
                    for (int a = 0; a < 8; ++a)
                        acc = cadd(acc, cmulc(tmpL[z][i0][a], G[t][z][a][j0]));
                rhoL[t + 1][i0][j0] = acc;
            } else {
                const int kR = NQ - 1 - t;
                float2 acc = make_float2(0.f, 0.f);
                #pragma unroll
                for (int z = 0; z < 2; ++z)
                    #pragma unroll
                    for (int a = 0; a < 8; ++a)
                        acc = cadd(acc, cmulc(tmpR[z][i0][a], G[kR][z][j0][a]));
                sigR[kR][i0][j0] = acc;
            }
        }
        __syncthreads();
    }

    // ---- <Z_w> = sum_z (-1)^z  (G[w][z]^T rho^(w) G[w][z]^*) . sigma^(w+1) ----
    // 8 threads per wire w; thread handles fixed middle index bb.
    if (tid < NQ * 8) {
        const int w  = tid >> 3;
        const int bb = tid & 7;
        float accRe = 0.f;
        #pragma unroll
        for (int z = 0; z < 2; ++z) {
            float2 zacc = make_float2(0.f, 0.f);
            #pragma unroll
            for (int be = 0; be < 8; ++be) {
                float2 v  = make_float2(0.f, 0.f);   // sum_a G[z][a][be] * rho[a][bb]
                float2 s2 = make_float2(0.f, 0.f);   // sum_a conj(G[z][bb][a]) * sig[be][a]
                #pragma unroll
                for (int a = 0; a < 8; ++a) {
                    v  = cadd(v,  cmul(G[w][z][a][be], rhoL[w][a][bb]));
                    s2 = cadd(s2, cmulc(sigR[w + 1][be][a], G[w][z][bb][a]));
                }
                zacc = cadd(zacc, cmul(v, s2));
            }
            accRe += (z == 0) ? zacc.x : -zacc.x;
        }
        zred[w][bb] = accRe;
    }
    __syncthreads();
    if (tid < NQ) {
        float sum = 0.f;
        #pragma unroll
        for (int j = 0; j < 8; ++j) sum += zred[tid][j];
        out[b * NQ + tid] = sum;
    }
}

extern "C" void kernel_launch(void* const* d_in, const int* in_sizes, int n_in,
                              void* d_out, int out_size)
{
    const float* x  = (const float*)d_in[0];   // input_vec (64,32)
    const float* vp = (const float*)d_in[1];   // var_params (3,18,2)
    // defensive: identify by element count (var_params = 108)
    if (n_in >= 2 && in_sizes[0] == NREPS * NQ * 2) {
        x  = (const float*)d_in[1];
        vp = (const float*)d_in[0];
    }
    qenc_kernel<<<NBATCH, 256>>>(x, vp, (float*)d_out);
}

// round 2
// speedup vs baseline: 1.2678x; 1.2678x over previous
#include <cuda_runtime.h>

#define NQ     18
#define NREPS  3
#define NBATCH 64
#define IDIM   32

__device__ __forceinline__ float2 cmul(float2 a, float2 b) {
    return make_float2(a.x * b.x - a.y * b.y, a.x * b.y + a.y * b.x);
}
__device__ __forceinline__ float2 cmulc(float2 a, float2 b) {   // a * conj(b)
    return make_float2(a.x * b.x + a.y * b.y, a.y * b.x - a.x * b.y);
}
__device__ __forceinline__ float2 cadd(float2 a, float2 b) {
    return make_float2(a.x + b.x, a.y + b.y);
}
__device__ __forceinline__ float2 csub(float2 a, float2 b) {
    return make_float2(a.x - b.x, a.y - b.y);
}

// One block per batch element. Exact MPS/transfer-matrix contraction:
//   - CNOT staircase == prefix-XOR basis permutation
//   - bond dimension exactly 8 = 2^REPS (one crossing gate per cut per rep)
//   - G_k[z] are 8x8; left/right 8x8 density environments give all <Z_w>.
// Sweep stage-2 additionally emits D[t] = sum_z (-1)^z tmpL[z] conj(G[t][z]),
// so <Z_t> = Re( D[t] . sigma^(t+1) )  -- no heavy epilogue.
__global__ __launch_bounds__(256, 1) void qenc_kernel(
    const float* __restrict__ xin,   // (64, 32) float32
    const float* __restrict__ vp,    // (3, 18, 2) float32
    float* __restrict__ out)         // (64, 18) float32
{
    const int b   = blockIdx.x;
    const int tid = threadIdx.x;

    __shared__ float2 G[NQ][2][8][8];        // site tensors G[k][z][p][n]
    __shared__ float2 rho[8][8];             // current left env (single buffer)
    __shared__ float2 sigR[NQ + 1][8][8];    // sigma^(1..18) at index k
    __shared__ float2 D[NQ][8][8];           // signed per-site matrices
    __shared__ float2 tmpL[2][8][8];
    __shared__ float2 tmpR[2][8][8];
    __shared__ float  scC[NQ][7];            // cos(theta/2): A1,B1,A2,B2,A3,B3,x
    __shared__ float  scS[NQ][7];            // sin(theta/2)
    __shared__ float  B3s[NQ][2][2];
    __shared__ float  C3s[NQ][2][2];         // A3 * B2
    __shared__ float  C2s[NQ][2][2];         // A2 * B1
    __shared__ float2 ws[NQ][2];             // A1 * u   (batch-dependent, complex)
    __shared__ float  zred[NQ][8];

    // ---- phase A: all sincos in parallel (126 threads, one each) ----------
    if (tid < NQ * 7) {
        const int k = tid / 7;
        const int g = tid - k * 7;
        float th;
        if (g < 6) {
            const int r = g >> 1, c = g & 1;
            th = vp[(r * NQ + k) * 2 + c];
        } else {
            th = xin[b * IDIM + k];
        }
        float s, c;
        __sincosf(0.5f * th, &s, &c);
        scC[k][g] = c;
        scS[k][g] = s;
    }
    __syncthreads();

    // ---- phase B: per-site 2x2 combos (18 threads) ------------------------
    if (tid < NQ) {
        const int k = tid;
        // RY(th) = [[c,-s],[s,c]]
        const float A1[2][2] = {{scC[k][0], -scS[k][0]}, {scS[k][0], scC[k][0]}};
        const float B1[2][2] = {{scC[k][1], -scS[k][1]}, {scS[k][1], scC[k][1]}};
        const float A2[2][2] = {{scC[k][2], -scS[k][2]}, {scS[k][2], scC[k][2]}};
        const float B2[2][2] = {{scC[k][3], -scS[k][3]}, {scS[k][3], scC[k][3]}};
        const float A3[2][2] = {{scC[k][4], -scS[k][4]}, {scS[k][4], scC[k][4]}};
        B3s[k][0][0] = scC[k][5];   B3s[k][0][1] = -scS[k][5];
        B3s[k][1][0] = scS[k][5];   B3s[k][1][1] = scC[k][5];
        #pragma unroll
        for (int i = 0; i < 2; ++i) {
            #pragma unroll
            for (int j = 0; j < 2; ++j) {
                C3s[k][i][j] = A3[i][0] * B2[0][j] + A3[i][1] * B2[1][j];
                C2s[k][i][j] = A2[i][0] * B1[0][j] + A2[i][1] * B1[1][j];
            }
        }
        // RX(x)|0> = (cos(x/2), -i sin(x/2));  w[s] = A1[s][0]*u0 + A1[s][1]*u1
        const float cx = scC[k][6], sx = scS[k][6];
        ws[k][0] = make_float2(A1[0][0] * cx, -A1[0][1] * sx);
        ws[k][1] = make_float2(A1[1][0] * cx, -A1[1][1] * sx);
    }
    // boundary inits can go before the barrier (no dependence on phase B)
    if (tid >= 128 && tid < 192) {
        const int j = tid - 128;
        rho[j >> 3][j & 7] = make_float2(j == 0 ? 1.f : 0.f, 0.f);
    } else if (tid >= 192) {
        const int j = tid - 192;
        sigR[NQ][j >> 3][j & 7] = make_float2(1.f, 0.f);
    }
    __syncthreads();

    // ---- build G[k][z] (8x8) ---------------------------------------------
    // bond index = t1 + 2*t2 + 4*t3 (intermediate post-permutation bits)
    #pragma unroll
    for (int ii = 0; ii < 9; ++ii) {
        const int i  = tid + ii * 256;
        const int k  = i >> 7;
        const int z  = (i >> 6) & 1;
        const int p  = (i >> 3) & 7;
        const int n  = i & 7;
        const int n1 = n & 1, n2 = (n >> 1) & 1, n3 = (n >> 2) & 1;
        const int p1 = p & 1, p2 = (p >> 1) & 1, p3 = (p >> 2) & 1;
        const float coef = B3s[k][z][n3] * C3s[k][n3 ^ p3][n2] * C2s[k][n2 ^ p2][n1];
        const float2 wv  = ws[k][n1 ^ p1];
        G[k][z][p][n] = make_float2(coef * wv.x, coef * wv.y);
    }
    __syncthreads();

    // ---- simultaneous left (threads 0..127) and right (128..255) sweeps ---
    // left runs 18 iterations (t=0..17, also emits D[t]); right runs 17.
    const int half = tid >> 7;
    const int lt   = tid & 127;
    const int z0   = lt >> 6;
    const int i0   = (lt >> 3) & 7;
    const int j0   = lt & 7;

    for (int t = 0; t < NQ; ++t) {
        // stage 1: tmpL[z] = G[t][z]^T * rho   |  tmpR[z] = G[17-t][z] * sigma
        if (half == 0) {
            float2 acc = make_float2(0.f, 0.f);
            #pragma unroll
            for (int a = 0; a < 8; ++a)
                acc = cadd(acc, cmul(G[t][z0][a][i0], rho[a][j0]));
            tmpL[z0][i0][j0] = acc;
        } else if (t < NQ - 1) {
            const int kR = NQ - 1 - t;
            float2 acc = make_float2(0.f, 0.f);
            #pragma unroll
            for (int a = 0; a < 8; ++a)
                acc = cadd(acc, cmul(G[kR][z0][i0][a], sigR[kR + 1][a][j0]));
            tmpR[z0][i0][j0] = acc;
        }
        __syncthreads();
        // stage 2: term[z] = tmpL[z]*conj(G[t][z]);
        //          rho' = term0+term1; D[t] = term0-term1
        //          sigma' = sum_z tmpR[z]*G^dag
        if (lt < 64) {
            if (half == 0) {
                float2 t0 = make_float2(0.f, 0.f);
                float2 t1 = make_float2(0.f, 0.f);
                #pragma unroll
                for (int a = 0; a < 8; ++a) {
                    t0 = cadd(t0, cmulc(tmpL[0][i0][a], G[t][0][a][j0]));
                    t1 = cadd(t1, cmulc(tmpL[1][i0][a], G[t][1][a][j0]));
                }
                D[t][i0][j0] = csub(t0, t1);
                if (t < NQ - 1) rho[i0][j0] = cadd(t0, t1);
            } else if (t < NQ - 1) {
                const int kR = NQ - 1 - t;
                float2 acc = make_float2(0.f, 0.f);
                #pragma unroll
                for (int z = 0; z < 2; ++z)
                    #pragma unroll
                    for (int a = 0; a < 8; ++a)
                        acc = cadd(acc, cmulc(tmpR[z][i0][a], G[kR][z][j0][a]));
                sigR[kR][i0][j0] = acc;
            }
        }
        __syncthreads();
    }

    // ---- <Z_w> = Re( D[w] . sigma^(w+1) )  (plain elementwise dot) --------
    if (tid < NQ * 8) {
        const int w = tid >> 3;
        const int i = tid & 7;
        float acc = 0.f;
        #pragma unroll
        for (int j = 0; j < 8; ++j) {
            const float2 d = D[w][i][j];
            const float2 s = sigR[w + 1][i][j];
            acc += d.x * s.x - d.y * s.y;
        }
        zred[w][i] = acc;
    }
    __syncthreads();
    if (tid < NQ) {
        float sum = 0.f;
        #pragma unroll
        for (int j = 0; j < 8; ++j) sum += zred[tid][j];
        out[b * NQ + tid] = sum;
    }
}

extern "C" void kernel_launch(void* const* d_in, const int* in_sizes, int n_in,
                              void* d_out, int out_size)
{
    const float* x  = (const float*)d_in[0];   // input_vec (64,32)
    const float* vp = (const float*)d_in[1];   // var_params (3,18,2)
    if (n_in >= 2 && in_sizes[0] == NREPS * NQ * 2) {
        x  = (const float*)d_in[1];
        vp = (const float*)d_in[0];
    }
    qenc_kernel<<<NBATCH, 256>>>(x, vp, (float*)d_out);
}